// round 16
// baseline (speedup 1.0000x reference)
#include <cuda_runtime.h>
#include <math.h>
#include <stdint.h>

#define T_STEPS 2048
#define BATCH   32
#define HID     256
#define CLUSTER 8
#define REC_CTAS 128            // 16 clusters x 8 CTAs
#define REC_THREADS 320         // 8 GEMV warps + 2 Zx-producer warps
#define RING    32              // Zx ring depth (steps)

// ============================================================================
// Single fused kernel: cluster recurrence + in-CTA Zx production.
// 16 clusters x 8 CTAs; cluster = 2 batches; CTA owns 32 units x 4 gates.
//  - GEMV warps 0-7: h-part, register weights (Wh) + FFMA2 (proven R14)
//  - tail: warps 2-3 (SMSP 2/3), combine + gates + c,h + DSMEM push
//  - producer warps 8-9 (SMSP 0/1): z_x(t) = x(t) @ Wx + b into SMEM ring
//  - exchange: per-source slice mbarriers + lane-paired st.async (R14)
//  - ping-pong named barriers 1/2 (race-free R14 proof); bar 4 = producers
// ============================================================================
__device__ __forceinline__ uint32_t smem_u32(const void* p) {
    uint32_t a;
    asm("{ .reg .u64 t; cvta.to.shared.u64 t, %1; cvt.u32.u64 %0, t; }"
        : "=r"(a) : "l"(p));
    return a;
}

__device__ __forceinline__ float fast_sigmoid(float z) {
    return __fdividef(1.f, 1.f + __expf(-z));
}
__device__ __forceinline__ float fast_tanh(float z) {
    return 1.f - __fdividef(2.f, __expf(2.f * z) + 1.f);
}

#define FMA2(d, a, b) \
    asm("fma.rn.f32x2 %0, %1, %2, %3;" : "=l"(d) : "l"(a), "l"(b), "l"(d))
#define ADD2(d, a, b) \
    asm("add.rn.f32x2 %0, %1, %2;" : "=l"(d) : "l"(a), "l"(b))

__device__ __forceinline__ unsigned long long pack_f2(float lo, float hi) {
    float2 f = make_float2(lo, hi);
    return *reinterpret_cast<unsigned long long*>(&f);
}
__device__ __forceinline__ float unpack_sum(unsigned long long v) {
    float2 f = *reinterpret_cast<float2*>(&v);
    return f.x + f.y;
}
__device__ __forceinline__ float2 unpack2(unsigned long long v) {
    return *reinterpret_cast<float2*>(&v);
}

__device__ __forceinline__ void st_release_shared(uint32_t addr, int v) {
    asm volatile("st.release.cta.shared::cta.b32 [%0], %1;"
                 :: "r"(addr), "r"(v) : "memory");
}
__device__ __forceinline__ int ld_acquire_shared(uint32_t addr) {
    int v;
    asm volatile("ld.acquire.cta.shared::cta.b32 %0, [%1];"
                 : "=r"(v) : "r"(addr) : "memory");
    return v;
}

// smem layout: 16 mbarriers (128B), then floats
#define NBARS       16                   // 8 src x 2 (ping-pong)
#define SLICE_TX    256                  // bytes per (src, boundary)
#define SW_FLOATS   (256 * 128)          // Wh staging, then Wx2 [k2][u][gh][4]
#define SH_FLOATS   (2 * 2 * 256)        // h [buf][b][k]  (st.async dest)
#define SP_FLOATS   (8 * 2 * 128)        // partials [ks][b][u*4+g], x2 bufs
#define SC_FLOATS   64                   // cell state [b][u]
#define SRING_FLOATS (RING * 2 * 128)    // z_x ring [slot][b][u][g]
#define SXS_FLOATS  (2 * 2 * 256)        // x staging [buf][b][k]
#define SFLAG_FLOATS 16                  // prod @0, cons_a @4, cons_b @8
#define SMEM_FLOATS (SW_FLOATS + SH_FLOATS + 2 * SP_FLOATS + SC_FLOATS + \
                     SRING_FLOATS + SXS_FLOATS + SFLAG_FLOATS)
#define SMEM_BYTES  (NBARS * 8 + SMEM_FLOATS * 4)

__global__ __launch_bounds__(REC_THREADS, 1) __cluster_dims__(CLUSTER, 1, 1)
void lstm_fused(const float* __restrict__ x,
                const float* __restrict__ Wf, const float* __restrict__ bf,
                const float* __restrict__ Wi, const float* __restrict__ bi,
                const float* __restrict__ Wo, const float* __restrict__ bo,
                const float* __restrict__ Wc, const float* __restrict__ bc,
                float* __restrict__ out)
{
    extern __shared__ float smem_raw[];
    float* s_W    = smem_raw + NBARS * 2;     // [256][128]
    float* s_h    = s_W + SW_FLOATS;          // [2][2][256]
    float* s_part = s_h + SH_FLOATS;          // [2][8][2][128]
    float* s_c    = s_part + 2 * SP_FLOATS;   // [2][32]
    float* s_ring = s_c + SC_FLOATS;          // [RING][2][128]
    float* s_xs   = s_ring + SRING_FLOATS;    // [2][2][256]
    float* s_flag = s_xs + SXS_FLOATS;        // prod/cons counters

    const int tid  = threadIdx.x;
    const int wid  = tid >> 5;
    const int lane = tid & 31;
    const int rank = blockIdx.x & (CLUSTER - 1);
    const int cid  = blockIdx.x >> 3;
    const int bb0  = cid * 2;
    const float* Wg[4] = {Wf, Wi, Wo, Wc};
    const float* BG[4] = {bf, bi, bo, bc};

    const uint32_t smem_base = smem_u32(smem_raw);
    const uint32_t sh_base   = smem_base + NBARS * 8 + SW_FLOATS * 4;
    const uint32_t flag_base = smem_base + NBARS * 8
        + (SW_FLOATS + SH_FLOATS + 2 * SP_FLOATS + SC_FLOATS
           + SRING_FLOATS + SXS_FLOATS) * 4;
    const uint32_t f_prod  = flag_base;
    const uint32_t f_consA = flag_base + 16;
    const uint32_t f_consB = flag_base + 32;
    #define BAR_ADDR(src, pp) (smem_base + (uint32_t)(((src) * 2 + (pp)) * 8))

    // ---- stage Wh (h-part rows 256..511) into s_W for the register hoist ----
    for (int idx = tid; idx < SW_FLOATS; idx += REC_THREADS) {
        int k = idx >> 7, pc = idx & 127;
        s_W[idx] = Wg[pc >> 5][(size_t)(256 + k) * 256 + rank * 32 + (pc & 31)];
    }
    for (int i = tid; i < SH_FLOATS; i += REC_THREADS) s_h[i] = 0.f;
    if (tid < 64) s_c[tid] = 0.f;
    if (tid == 0) {
        *(int*)&s_flag[0] = 0;    // prod
        *(int*)&s_flag[4] = 0;    // cons_a
        *(int*)&s_flag[8] = 0;    // cons_b
        #pragma unroll
        for (int i = 0; i < NBARS; i++) {
            uint32_t b = smem_base + (uint32_t)(i * 8);
            asm volatile("mbarrier.init.shared.b64 [%0], 1;" :: "r"(b) : "memory");
            asm volatile("mbarrier.arrive.expect_tx.shared.b64 _, [%0], %1;"
                         :: "r"(b), "r"(SLICE_TX) : "memory");
        }
    }
    __syncthreads();

    // ---- GEMV warps hoist Wh to registers (unit-major, k-parity packed) ----
    const int ks   = wid;                 // valid for wid<8
    const int colq = lane;
    unsigned long long wreg[4][16];
    if (wid < 8) {
        #pragma unroll
        for (int c = 0; c < 4; c++)
            #pragma unroll
            for (int p = 0; p < 16; p++)
                wreg[c][p] = pack_f2(
                    s_W[(ks * 32 + 2 * p)     * 128 + c * 32 + colq],
                    s_W[(ks * 32 + 2 * p + 1) * 128 + c * 32 + colq]);
    }
    __syncthreads();                      // hoist reads done

    // ---- overwrite s_W with Wx2: [k2][u][gh][(g&1)k-pair quad] ----
    // offset = k2*256 + u*8 + gh*4 + j ; g = gh*2 + (j>>1), k01 = j&1
    for (int idx = tid; idx < SW_FLOATS; idx += REC_THREADS) {
        int k2 = idx >> 8, rem = idx & 255;
        int u = rem >> 3, q = rem & 7;
        int gh = q >> 2, j = q & 3;
        int g = gh * 2 + (j >> 1), k01 = j & 1;
        s_W[idx] = Wg[g][(size_t)(2 * k2 + k01) * 256 + rank * 32 + u];
    }
    __syncthreads();
    asm volatile("barrier.cluster.arrive.aligned;" ::: "memory");
    asm volatile("barrier.cluster.wait.aligned;" ::: "memory");

    if (wid >= 8) {
        // ================= Zx producer warps (SMSP 0/1) =================
        const int gt = (wid - 8) * 32 + lane;   // 0..63
        const int gb = gt & 1;                  // batch for compute
        const int gu = gt >> 1;                 // unit 0..31
        const int lb = gt >> 5;                 // batch for x staging
        const int lk = (gt & 31) * 8;           // k offset for x staging

        float b4[4];
        #pragma unroll
        for (int g = 0; g < 4; g++) b4[g] = BG[g][rank * 32 + gu];

        // prolog: stage x(0)
        {
            const float* xp = x + ((size_t)(bb0 + lb) * T_STEPS + 0) * 256 + lk;
            float4 a0 = __ldg(reinterpret_cast<const float4*>(xp));
            float4 a1 = __ldg(reinterpret_cast<const float4*>(xp + 4));
            float* xd = s_xs + lb * 256 + lk;
            *reinterpret_cast<float4*>(xd)     = a0;
            *reinterpret_cast<float4*>(xd + 4) = a1;
        }
        asm volatile("bar.sync 4, 64;" ::: "memory");

        int cons_seen = 0;
        for (int t = 0; t < T_STEPS; t++) {
            // backpressure: slot t&31 reusable once both consumers passed t-32
            while (cons_seen < t - (RING - 1)) {
                int a = ld_acquire_shared(f_consA);
                int b = ld_acquire_shared(f_consB);
                cons_seen = (a < b) ? a : b;
            }
            // prefetch x(t+1)
            float4 n0, n1;
            if (t + 1 < T_STEPS) {
                const float* xp = x + ((size_t)(bb0 + lb) * T_STEPS + (t + 1)) * 256 + lk;
                n0 = __ldg(reinterpret_cast<const float4*>(xp));
                n1 = __ldg(reinterpret_cast<const float4*>(xp + 4));
            }
            // z(t)[gb][gu][0..3] = b4 + sum_k x * Wx
            unsigned long long a0 = pack_f2(b4[0], 0.f);
            unsigned long long a1 = pack_f2(b4[1], 0.f);
            unsigned long long a2 = pack_f2(b4[2], 0.f);
            unsigned long long a3 = pack_f2(b4[3], 0.f);
            const float* xrow = s_xs + (t & 1) * 512 + gb * 256;
            const float* wrow = s_W + gu * 8;
            #pragma unroll 8
            for (int k2 = 0; k2 < 128; k2++) {
                unsigned long long xk =
                    *reinterpret_cast<const unsigned long long*>(xrow + 2 * k2);
                ulonglong2 wA = *reinterpret_cast<const ulonglong2*>(wrow + k2 * 256);
                ulonglong2 wB = *reinterpret_cast<const ulonglong2*>(wrow + k2 * 256 + 4);
                FMA2(a0, wA.x, xk);
                FMA2(a1, wA.y, xk);
                FMA2(a2, wB.x, xk);
                FMA2(a3, wB.y, xk);
            }
            float4 zr;
            zr.x = unpack_sum(a0); zr.y = unpack_sum(a1);
            zr.z = unpack_sum(a2); zr.w = unpack_sum(a3);
            *reinterpret_cast<float4*>(
                s_ring + ((t & (RING - 1)) * 2 + gb) * 128 + gu * 4) = zr;
            // stage x(t+1)
            if (t + 1 < T_STEPS) {
                float* xd = s_xs + ((t + 1) & 1) * 512 + lb * 256 + lk;
                *reinterpret_cast<float4*>(xd)     = n0;
                *reinterpret_cast<float4*>(xd + 4) = n1;
            }
            asm volatile("bar.sync 4, 64;" ::: "memory");
            if (gt == 0) st_release_shared(f_prod, t + 1);
        }
    } else {
        // ================= recurrence warps 0-7 (R14 protocol) =============
        const bool is_tail = (wid == 2 || wid == 3);   // SMSP 2/3
        const int tb = wid - 2;                        // batch (tail only)
        const int tu = lane;

        int par0 = 0, par1 = 0;
        int prod_seen = 0;

        for (int t = 0; t < T_STEPS; t++) {
            const int cbuf = t & 1, nbuf = cbuf ^ 1;

            // wait for THIS warp's slice (boundary t), t >= 1
            if (t >= 1) {
                const uint32_t bar = BAR_ADDR(ks, cbuf);
                const int par = cbuf ? par1 : par0;
                uint32_t done = 0;
                do {
                    asm volatile(
                        "{\n\t.reg .pred p;\n\t"
                        "mbarrier.try_wait.parity.acquire.cta.shared::cta.b64 "
                        "p, [%1], %2, 0x989680;\n\t"
                        "selp.b32 %0, 1, 0, p;\n\t}"
                        : "=r"(done) : "r"(bar), "r"(par) : "memory");
                } while (!done);
                if (cbuf) par1 ^= 1; else par0 ^= 1;
                if (lane == 0 && t + 2 < T_STEPS) {
                    asm volatile("mbarrier.arrive.expect_tx.shared.b64 _, [%0], %1;"
                                 :: "r"(bar), "r"(SLICE_TX) : "memory");
                }
            }

            // GEMV: 4 gates x 2 batches x 32 k; reg weights, FFMA2
            {
                const float* hb0 = s_h + (cbuf * 2) * 256 + ks * 32;
                const float* hb1 = hb0 + 256;
                unsigned long long acc[4][2];
                #pragma unroll
                for (int c = 0; c < 4; c++) { acc[c][0] = 0ull; acc[c][1] = 0ull; }

                #pragma unroll
                for (int j = 0; j < 8; j++) {
                    ulonglong2 H0 = *reinterpret_cast<const ulonglong2*>(hb0 + j * 4);
                    ulonglong2 H1 = *reinterpret_cast<const ulonglong2*>(hb1 + j * 4);
                    #pragma unroll
                    for (int c = 0; c < 4; c++) {
                        FMA2(acc[c][0], wreg[c][2 * j],     H0.x);
                        FMA2(acc[c][0], wreg[c][2 * j + 1], H0.y);
                        FMA2(acc[c][1], wreg[c][2 * j],     H1.x);
                        FMA2(acc[c][1], wreg[c][2 * j + 1], H1.y);
                    }
                }
                float* pw = s_part + cbuf * SP_FLOATS + (ks * 2) * 128 + colq * 4;
                float4 A0, A1;
                A0.x = unpack_sum(acc[0][0]); A0.y = unpack_sum(acc[1][0]);
                A0.z = unpack_sum(acc[2][0]); A0.w = unpack_sum(acc[3][0]);
                A1.x = unpack_sum(acc[0][1]); A1.y = unpack_sum(acc[1][1]);
                A1.z = unpack_sum(acc[2][1]); A1.w = unpack_sum(acc[3][1]);
                *reinterpret_cast<float4*>(pw)       = A0;
                *reinterpret_cast<float4*>(pw + 128) = A1;
            }

            // ping-pong producer/consumer barrier (race-free R14 scheme)
            if (is_tail) {
                asm volatile("bar.sync %0, 256;" :: "r"(1 + cbuf) : "memory");

                // z_x from ring (produced in-CTA)
                if (prod_seen <= t) {
                    do { prod_seen = ld_acquire_shared(f_prod); }
                    while (prod_seen <= t);
                }
                float4 z4 = *reinterpret_cast<const float4*>(
                    s_ring + ((t & (RING - 1)) * 2 + tb) * 128 + tu * 4);
                __syncwarp();
                if (lane == 0)
                    st_release_shared(tb == 0 ? f_consA : f_consB, t + 1);

                // tree-reduced combine + gates + c,h
                unsigned long long lo[8], hi[8];
                const float* pb = s_part + cbuf * SP_FLOATS + tb * 128 + tu * 4;
                #pragma unroll
                for (int q = 0; q < 8; q++) {
                    ulonglong2 v = *reinterpret_cast<const ulonglong2*>(pb + q * 256);
                    lo[q] = v.x; hi[q] = v.y;
                }
                ADD2(lo[0], lo[0], lo[1]); ADD2(lo[2], lo[2], lo[3]);
                ADD2(lo[4], lo[4], lo[5]); ADD2(lo[6], lo[6], lo[7]);
                ADD2(hi[0], hi[0], hi[1]); ADD2(hi[2], hi[2], hi[3]);
                ADD2(hi[4], hi[4], hi[5]); ADD2(hi[6], hi[6], hi[7]);
                ADD2(lo[0], lo[0], lo[2]); ADD2(lo[4], lo[4], lo[6]);
                ADD2(hi[0], hi[0], hi[2]); ADD2(hi[4], hi[4], hi[6]);
                ADD2(lo[0], lo[0], lo[4]);
                ADD2(hi[0], hi[0], hi[4]);
                unsigned long long zlo = pack_f2(z4.x, z4.y);   // (f, i)
                unsigned long long zhi = pack_f2(z4.z, z4.w);   // (o, c)
                ADD2(zlo, zlo, lo[0]);
                ADD2(zhi, zhi, hi[0]);

                float2 zfi = unpack2(zlo);
                float2 zoc = unpack2(zhi);
                float fg = fast_sigmoid(zfi.x);
                float ig = fast_sigmoid(zfi.y);
                float og = fast_sigmoid(zoc.x);
                float gg = fast_tanh(zoc.y);
                float cv = fmaf(fg, s_c[tb * 32 + tu], ig * gg);
                s_c[tb * 32 + tu] = cv;
                float hv = og * fast_tanh(cv);

                // push FIRST: lane-paired 8B st.async to all 8 ranks
                if (t + 1 < T_STEPS) {
                    float hp = __shfl_xor_sync(0xffffffffu, hv, 1);
                    if ((tu & 1) == 0) {
                        double val;
                        {
                            float2 f2 = make_float2(hv, hp);
                            val = *reinterpret_cast<double*>(&f2);
                        }
                        uint32_t daddr = sh_base
                            + (uint32_t)(((nbuf * 2 + tb) * 256 + rank * 32 + tu) * 4);
                        uint32_t baddr = BAR_ADDR(rank, nbuf);
                        #pragma unroll
                        for (int p = 0; p < CLUSTER; p++) {
                            asm volatile(
                                "{\n\t.reg .b32 ra, rb;\n\t"
                                "mapa.shared::cluster.u32 ra, %0, %2;\n\t"
                                "mapa.shared::cluster.u32 rb, %1, %2;\n\t"
                                "st.async.shared::cluster.mbarrier::complete_tx::bytes.b64 "
                                "[ra], %3, [rb];\n\t}"
                                :: "r"(daddr), "r"(baddr), "r"(p), "d"(val)
                                : "memory");
                        }
                    }
                }

                // output (fire-and-forget); reverse time order
                out[((size_t)(bb0 + tb) * T_STEPS + (T_STEPS - 1 - t)) * HID
                    + rank * 32 + tu] = hv;
            } else {
                // producers (GEMV-only warps): non-blocking arrive on bar(cbuf)
                asm volatile("bar.arrive %0, 256;" :: "r"(1 + cbuf) : "memory");
            }
        }
    }

    // DSMEM discipline: no CTA exits while peers could still target it
    asm volatile("barrier.cluster.arrive.aligned;" ::: "memory");
    asm volatile("barrier.cluster.wait.aligned;" ::: "memory");
}

// ============================================================================
extern "C" void kernel_launch(void* const* d_in, const int* in_sizes, int n_in,
                              void* d_out, int out_size)
{
    const float* x  = (const float*)d_in[0];
    const float* Wf = (const float*)d_in[1];
    const float* bf = (const float*)d_in[2];
    const float* Wi = (const float*)d_in[3];
    const float* bi = (const float*)d_in[4];
    const float* Wo = (const float*)d_in[5];
    const float* bo = (const float*)d_in[6];
    const float* Wc = (const float*)d_in[7];
    const float* bc = (const float*)d_in[8];
    float* out = (float*)d_out;

    cudaFuncSetAttribute(lstm_fused,
                         cudaFuncAttributeMaxDynamicSharedMemorySize, SMEM_BYTES);

    lstm_fused<<<REC_CTAS, REC_THREADS, SMEM_BYTES>>>(
        x, Wf, bf, Wi, bi, Wo, bo, Wc, bc, out);
}

// round 17
// speedup vs baseline: 2.0960x; 2.0960x over previous
#include <cuda_runtime.h>
#include <math.h>
#include <stdint.h>

#define T_STEPS 2048
#define BATCH   32
#define HID     256
#define ZCOLS   1024            // 4*HID, gate order f,i,o,c
#define MROWS   (T_STEPS * BATCH)
#define CLUSTER 8
#define REC_CTAS 128            // 16 clusters x 8 CTAs
#define REC_THREADS 256

// ---------------- scratch (device globals: no allocations allowed) ----------
__device__ float g_Zx[(size_t)MROWS * ZCOLS];   // row-major: Zx[t*32+b][col]

__device__ __forceinline__ unsigned long long pack_f2(float lo, float hi) {
    float2 f = make_float2(lo, hi);
    return *reinterpret_cast<unsigned long long*>(&f);
}
__device__ __forceinline__ float unpack_sum(unsigned long long v) {
    float2 f = *reinterpret_cast<float2*>(&v);
    return f.x + f.y;
}
__device__ __forceinline__ float2 unpack2(unsigned long long v) {
    return *reinterpret_cast<float2*>(&v);
}

#define FMA2(d, a, b) \
    asm("fma.rn.f32x2 %0, %1, %2, %3;" : "=l"(d) : "l"(a), "l"(b), "l"(d))
#define ADD2(d, a, b) \
    asm("add.rn.f32x2 %0, %1, %2;" : "=l"(d) : "l"(a), "l"(b))

// ============================================================================
// Kernel 1: Zx[t*32+b][g*256+j] = sum_k x[b][t][k] * Wg[k][j] + bg[j]
// 128x128 tile SGEMM, BK=16, 256 threads, 8x8 microtile — FFMA2-packed:
// As stored as duplicated (a,a) 64-bit entries, Bs pairs natural over n,
// accumulators packed over n. Per k: 8 LDS + 32 FFMA2 (vs 4 LDS + 64 FFMA).
// ============================================================================
__global__ __launch_bounds__(256, 2)
void gemm_zx(const float* __restrict__ x,
             const float* __restrict__ Wf, const float* __restrict__ bf,
             const float* __restrict__ Wi, const float* __restrict__ bi,
             const float* __restrict__ Wo, const float* __restrict__ bo,
             const float* __restrict__ Wc, const float* __restrict__ bc)
{
    __shared__ unsigned long long As2[16 * 128];  // [k][m] dup (a,a), 16KB
    __shared__ float Bs[16 * 128];                // [k][n], 8KB

    const int t = threadIdx.x;

    const float* Wg[4] = {Wf, Wi, Wo, Wc};
    const float* bg[4] = {bf, bi, bo, bc};

    const int N0 = blockIdx.x * 128;          // never straddles a gate
    const int gate = N0 >> 8;
    const int jb = N0 & 255;
    const float* __restrict__ W = Wg[gate];

    const int M0 = blockIdx.y * 128;
    const int tx = t & 15;
    const int ty = t >> 4;

    unsigned long long acc2[8][4];            // [m][n-pair]
    #pragma unroll
    for (int i = 0; i < 8; i++)
        #pragma unroll
        for (int j = 0; j < 4; j++) acc2[i][j] = 0ull;

    for (int k0 = 0; k0 < 256; k0 += 16) {
        #pragma unroll
        for (int i = 0; i < 2; i++) {
            int f = t + i * 256;
            int kq  = f >> 7;
            int row = f & 127;
            int m   = M0 + row;
            int bb  = m & 31;
            int tt  = m >> 5;
            float4 a = *reinterpret_cast<const float4*>(
                x + ((size_t)bb * T_STEPS + tt) * 256 + k0 + kq * 4);
            As2[(kq * 4 + 0) * 128 + row] = pack_f2(a.x, a.x);
            As2[(kq * 4 + 1) * 128 + row] = pack_f2(a.y, a.y);
            As2[(kq * 4 + 2) * 128 + row] = pack_f2(a.z, a.z);
            As2[(kq * 4 + 3) * 128 + row] = pack_f2(a.w, a.w);
            int kk = f >> 5;
            int nq = f & 31;
            *reinterpret_cast<float4*>(&Bs[kk * 128 + nq * 4]) =
                *reinterpret_cast<const float4*>(W + (size_t)(k0 + kk) * 256 + jb + nq * 4);
        }
        __syncthreads();

        #pragma unroll
        for (int k = 0; k < 16; k++) {
            ulonglong2 a01 = *reinterpret_cast<const ulonglong2*>(&As2[k * 128 + ty * 8]);
            ulonglong2 a23 = *reinterpret_cast<const ulonglong2*>(&As2[k * 128 + ty * 8 + 2]);
            ulonglong2 a45 = *reinterpret_cast<const ulonglong2*>(&As2[k * 128 + ty * 8 + 4]);
            ulonglong2 a67 = *reinterpret_cast<const ulonglong2*>(&As2[k * 128 + ty * 8 + 6]);
            ulonglong2 b03 = *reinterpret_cast<const ulonglong2*>(&Bs[k * 128 + tx * 8]);
            ulonglong2 b47 = *reinterpret_cast<const ulonglong2*>(&Bs[k * 128 + tx * 8 + 4]);
            unsigned long long ad[8] = {a01.x, a01.y, a23.x, a23.y,
                                        a45.x, a45.y, a67.x, a67.y};
            unsigned long long bp[4] = {b03.x, b03.y, b47.x, b47.y};
            #pragma unroll
            for (int i = 0; i < 8; i++) {
                FMA2(acc2[i][0], ad[i], bp[0]);
                FMA2(acc2[i][1], ad[i], bp[1]);
                FMA2(acc2[i][2], ad[i], bp[2]);
                FMA2(acc2[i][3], ad[i], bp[3]);
            }
        }
        __syncthreads();
    }

    // epilogue: packed bias add, packed stores
    const float* __restrict__ bias = bg[gate];
    unsigned long long bpair[4];
    #pragma unroll
    for (int jp = 0; jp < 4; jp++)
        bpair[jp] = *reinterpret_cast<const unsigned long long*>(
            bias + jb + tx * 8 + 2 * jp);
    #pragma unroll
    for (int i = 0; i < 8; i++) {
        int m = M0 + ty * 8 + i;
        float* zr = g_Zx + (size_t)m * ZCOLS + N0 + tx * 8;
        ADD2(acc2[i][0], acc2[i][0], bpair[0]);
        ADD2(acc2[i][1], acc2[i][1], bpair[1]);
        ADD2(acc2[i][2], acc2[i][2], bpair[2]);
        ADD2(acc2[i][3], acc2[i][3], bpair[3]);
        ulonglong2 v0; v0.x = acc2[i][0]; v0.y = acc2[i][1];
        ulonglong2 v1; v1.x = acc2[i][2]; v1.y = acc2[i][3];
        *reinterpret_cast<ulonglong2*>(zr)     = v0;
        *reinterpret_cast<ulonglong2*>(zr + 4) = v1;
    }
}

// ============================================================================
// Kernel 2: cluster recurrence — race-free R14 exactly, with cell state in
// registers (tail threads are persistent; removes LDS from the tail chain).
// ============================================================================
__device__ __forceinline__ uint32_t smem_u32(const void* p) {
    uint32_t a;
    asm("{ .reg .u64 t; cvta.to.shared.u64 t, %1; cvt.u32.u64 %0, t; }"
        : "=r"(a) : "l"(p));
    return a;
}

__device__ __forceinline__ float fast_sigmoid(float z) {
    return __fdividef(1.f, 1.f + __expf(-z));
}
__device__ __forceinline__ float fast_tanh(float z) {
    return 1.f - __fdividef(2.f, __expf(2.f * z) + 1.f);
}

// smem layout: 16 mbarriers (128B), then floats
#define NBARS       16                   // 8 src x 2 (ping-pong)
#define SLICE_TX    256                  // bytes per (src, boundary)
#define SW_FLOATS   (256 * 128)          // weights [k][gate*32+unit] (staging)
#define SH_FLOATS   (2 * 2 * 256)        // h [buf][b][k]  (st.async dest)
#define SP_FLOATS   (8 * 2 * 128)        // partials [ks][b][unit*4+gate], x2
#define SMEM_FLOATS (SW_FLOATS + SH_FLOATS + 2 * SP_FLOATS)
#define SMEM_BYTES  (NBARS * 8 + SMEM_FLOATS * 4)

__global__ __launch_bounds__(REC_THREADS, 1) __cluster_dims__(CLUSTER, 1, 1)
void lstm_rec(const float* __restrict__ Wf, const float* __restrict__ Wi,
              const float* __restrict__ Wo, const float* __restrict__ Wc,
              float* __restrict__ out)
{
    extern __shared__ float smem_raw[];
    float* s_W    = smem_raw + NBARS * 2;     // [256][128] (staging)
    float* s_h    = s_W + SW_FLOATS;          // [2][2][256]
    float* s_part = s_h + SH_FLOATS;          // [2][8][2][32 units][4 gates]

    const int tid  = threadIdx.x;
    const int wid  = tid >> 5;
    const int lane = tid & 31;
    const int rank = blockIdx.x & (CLUSTER - 1);
    const int cid  = blockIdx.x >> 3;
    const int bb0  = cid * 2;
    const float* Wg[4] = {Wf, Wi, Wo, Wc};

    const uint32_t smem_base = smem_u32(smem_raw);
    const uint32_t sh_base = smem_base + NBARS * 8 + SW_FLOATS * 4;
    #define BAR_ADDR(src, pp) (smem_base + (uint32_t)(((src) * 2 + (pp)) * 8))

    // stage weights once: s_W[k][pc] = Wg[pc>>5][(256+k)*256 + rank*32 + (pc&31)]
    for (int idx = tid; idx < SW_FLOATS; idx += REC_THREADS) {
        int k = idx >> 7, pc = idx & 127;
        s_W[idx] = Wg[pc >> 5][(size_t)(256 + k) * 256 + rank * 32 + (pc & 31)];
    }
    for (int i = tid; i < SH_FLOATS; i += REC_THREADS) s_h[i] = 0.f;

    if (tid == 0) {
        #pragma unroll
        for (int i = 0; i < NBARS; i++) {
            uint32_t b = smem_base + (uint32_t)(i * 8);
            asm volatile("mbarrier.init.shared.b64 [%0], 1;" :: "r"(b) : "memory");
            asm volatile("mbarrier.arrive.expect_tx.shared.b64 _, [%0], %1;"
                         :: "r"(b), "r"(SLICE_TX) : "memory");
        }
    }
    __syncthreads();

    // GEMV roles: warp ks (32 k's = src ks's slice), lane colq = UNIT 0..31
    const int ks   = wid;
    const int colq = lane;

    // hoist 128 weights to regs, packed over k-parity; gate c of unit colq
    unsigned long long wreg[4][16];
    #pragma unroll
    for (int c = 0; c < 4; c++)
        #pragma unroll
        for (int p = 0; p < 16; p++)
            wreg[c][p] = pack_f2(
                s_W[(ks * 32 + 2 * p)     * 128 + c * 32 + colq],
                s_W[(ks * 32 + 2 * p + 1) * 128 + c * 32 + colq]);

    asm volatile("barrier.cluster.arrive.aligned;" ::: "memory");
    asm volatile("barrier.cluster.wait.aligned;" ::: "memory");

    // tail roles (tid < 64): tb = batch, tu = unit; c lives in a register
    const int tb = tid >> 5;
    const int tu = tid & 31;
    float creg = 0.f;

    // per-warp parity state (slice barrier ping-pong)
    int par0 = 0, par1 = 0;

    // Zx prefetch (tail threads): gates f,i,o,c for (tb, tu)
    float pf[4];
    if (tid < 64) {
        const float* z = g_Zx + ((size_t)0 * 32 + bb0 + tb) * ZCOLS + rank * 32 + tu;
        #pragma unroll
        for (int g = 0; g < 4; g++) pf[g] = __ldcg(z + g * 256);
    }

    for (int t = 0; t < T_STEPS; t++) {
        const int cbuf = t & 1, nbuf = cbuf ^ 1;

        // wait for THIS warp's slice (boundary t), t >= 1
        if (t >= 1) {
            const uint32_t bar = BAR_ADDR(ks, cbuf);
            const int par = cbuf ? par1 : par0;
            uint32_t done = 0;
            do {
                asm volatile(
                    "{\n\t.reg .pred p;\n\t"
                    "mbarrier.try_wait.parity.acquire.cta.shared::cta.b64 "
                    "p, [%1], %2, 0x989680;\n\t"
                    "selp.b32 %0, 1, 0, p;\n\t}"
                    : "=r"(done) : "r"(bar), "r"(par) : "memory");
            } while (!done);
            if (cbuf) par1 ^= 1; else par0 ^= 1;
            if (lane == 0 && t + 2 < T_STEPS) {
                asm volatile("mbarrier.arrive.expect_tx.shared.b64 _, [%0], %1;"
                             :: "r"(bar), "r"(SLICE_TX) : "memory");
            }
        }

        // GEMV: 4 gates x 2 batches x 32 k; reg weights, FFMA2
        {
            const float* hb0 = s_h + (cbuf * 2) * 256 + ks * 32;
            const float* hb1 = hb0 + 256;
            unsigned long long acc[4][2];
            #pragma unroll
            for (int c = 0; c < 4; c++) { acc[c][0] = 0ull; acc[c][1] = 0ull; }

            #pragma unroll
            for (int j = 0; j < 8; j++) {
                ulonglong2 H0 = *reinterpret_cast<const ulonglong2*>(hb0 + j * 4);
                ulonglong2 H1 = *reinterpret_cast<const ulonglong2*>(hb1 + j * 4);
                #pragma unroll
                for (int c = 0; c < 4; c++) {
                    FMA2(acc[c][0], wreg[c][2 * j],     H0.x);
                    FMA2(acc[c][0], wreg[c][2 * j + 1], H0.y);
                    FMA2(acc[c][1], wreg[c][2 * j],     H1.x);
                    FMA2(acc[c][1], wreg[c][2 * j + 1], H1.y);
                }
            }
            // unit-major store: float4 = (f,i,o,c) partials of unit colq
            float* pw = s_part + cbuf * SP_FLOATS + (ks * 2) * 128 + colq * 4;
            float4 A0, A1;
            A0.x = unpack_sum(acc[0][0]); A0.y = unpack_sum(acc[1][0]);
            A0.z = unpack_sum(acc[2][0]); A0.w = unpack_sum(acc[3][0]);
            A1.x = unpack_sum(acc[0][1]); A1.y = unpack_sum(acc[1][1]);
            A1.z = unpack_sum(acc[2][1]); A1.w = unpack_sum(acc[3][1]);
            *reinterpret_cast<float4*>(pw)       = A0;
            *reinterpret_cast<float4*>(pw + 128) = A1;
        }

        // ping-pong producer/consumer barrier (race-free R14 scheme)
        if (tid < 64) {
            asm volatile("bar.sync %0, %1;"
                         :: "r"(1 + cbuf), "r"(REC_THREADS) : "memory");

            // fused tail: tree-reduced combine + gates + c,h + push + out
            unsigned long long lo[8], hi[8];
            const float* pb = s_part + cbuf * SP_FLOATS + tb * 128 + tu * 4;
            #pragma unroll
            for (int q = 0; q < 8; q++) {
                ulonglong2 v = *reinterpret_cast<const ulonglong2*>(pb + q * 256);
                lo[q] = v.x; hi[q] = v.y;
            }
            ADD2(lo[0], lo[0], lo[1]); ADD2(lo[2], lo[2], lo[3]);
            ADD2(lo[4], lo[4], lo[5]); ADD2(lo[6], lo[6], lo[7]);
            ADD2(hi[0], hi[0], hi[1]); ADD2(hi[2], hi[2], hi[3]);
            ADD2(hi[4], hi[4], hi[5]); ADD2(hi[6], hi[6], hi[7]);
            ADD2(lo[0], lo[0], lo[2]); ADD2(lo[4], lo[4], lo[6]);
            ADD2(hi[0], hi[0], hi[2]); ADD2(hi[4], hi[4], hi[6]);
            ADD2(lo[0], lo[0], lo[4]);
            ADD2(hi[0], hi[0], hi[4]);
            unsigned long long zlo = pack_f2(pf[0], pf[1]);   // (f, i)
            unsigned long long zhi = pack_f2(pf[2], pf[3]);   // (o, c)
            ADD2(zlo, zlo, lo[0]);
            ADD2(zhi, zhi, hi[0]);

            float2 zfi = unpack2(zlo);
            float2 zoc = unpack2(zhi);
            float fg = fast_sigmoid(zfi.x);
            float ig = fast_sigmoid(zfi.y);
            float og = fast_sigmoid(zoc.x);
            float gg = fast_tanh(zoc.y);
            creg = fmaf(fg, creg, ig * gg);
            float hv = og * fast_tanh(creg);

            // push FIRST (unblocks peers): lane-paired 8B st.async to 8 ranks
            if (t + 1 < T_STEPS) {
                float hp = __shfl_xor_sync(0xffffffffu, hv, 1);
                if ((tu & 1) == 0) {
                    double val;
                    {
                        float2 f2 = make_float2(hv, hp);
                        val = *reinterpret_cast<double*>(&f2);
                    }
                    uint32_t daddr = sh_base
                        + (uint32_t)(((nbuf * 2 + tb) * 256 + rank * 32 + tu) * 4);
                    uint32_t baddr = BAR_ADDR(rank, nbuf);
                    #pragma unroll
                    for (int p = 0; p < CLUSTER; p++) {
                        asm volatile(
                            "{\n\t.reg .b32 ra, rb;\n\t"
                            "mapa.shared::cluster.u32 ra, %0, %2;\n\t"
                            "mapa.shared::cluster.u32 rb, %1, %2;\n\t"
                            "st.async.shared::cluster.mbarrier::complete_tx::bytes.b64 "
                            "[ra], %3, [rb];\n\t}"
                            :: "r"(daddr), "r"(baddr), "r"(p), "d"(val) : "memory");
                    }
                }
            }

            // output (fire-and-forget)
            out[((size_t)(bb0 + tb) * T_STEPS + (T_STEPS - 1 - t)) * HID
                + rank * 32 + tu] = hv;

            // prefetch Zx(t+1)
            if (t + 1 < T_STEPS) {
                const float* z = g_Zx + ((size_t)(t + 1) * 32 + bb0 + tb) * ZCOLS
                               + rank * 32 + tu;
                #pragma unroll
                for (int g = 0; g < 4; g++) pf[g] = __ldcg(z + g * 256);
            }
        } else {
            // producers: non-blocking arrive on bar(cbuf); next arrive is on
            // bar(nbuf); return to bar(cbuf) at t+2 transitively requires this
            // CTA's step-t tail -> no phase mixing (R14 proof).
            asm volatile("bar.arrive %0, %1;"
                         :: "r"(1 + cbuf), "r"(REC_THREADS) : "memory");
        }
        // s_part double-buffered; s_h ping-pong: t+2 overwrites transitively
        // ordered after this CTA's tail of step t via the exchange chain.
    }

    // DSMEM discipline: no CTA exits while peers could still target it
    asm volatile("barrier.cluster.arrive.aligned;" ::: "memory");
    asm volatile("barrier.cluster.wait.aligned;" ::: "memory");
}

// ============================================================================
extern "C" void kernel_launch(void* const* d_in, const int* in_sizes, int n_in,
                              void* d_out, int out_size)
{
    const float* x  = (const float*)d_in[0];
    const float* Wf = (const float*)d_in[1];
    const float* bf = (const float*)d_in[2];
    const float* Wi = (const float*)d_in[3];
    const float* bi = (const float*)d_in[4];
    const float* Wo = (const float*)d_in[5];
    const float* bo = (const float*)d_in[6];
    const float* Wc = (const float*)d_in[7];
    const float* bc = (const float*)d_in[8];
    float* out = (float*)d_out;

    cudaFuncSetAttribute(lstm_rec,
                         cudaFuncAttributeMaxDynamicSharedMemorySize, SMEM_BYTES);

    dim3 g1(ZCOLS / 128, MROWS / 128);   // 8 x 512
    gemm_zx<<<g1, 256>>>(x, Wf, bf, Wi, bi, Wo, bo, Wc, bc);
    lstm_rec<<<REC_CTAS, REC_THREADS, SMEM_BYTES>>>(Wf, Wi, Wo, Wc, out);
}